// round 11
// baseline (speedup 1.0000x reference)
#include <cuda_runtime.h>
#include <cuda_fp16.h>
#include <math.h>
#include <stdint.h>

#define HID   512
#define PH    32
#define BSZ   2048
#define FOURH 2048
#define SLAB  (BSZ * HID)

#define TM 128
#define TN 128
#define KC 64
#define NCH (HID / KC)   // 8 k-chunks
#define NTHR 256
#define NCTA 256

// stage layout (bytes): A 128x64 fp16 = 16KB, B 128x64 fp16 = 16KB
#define AH_OFF 0
#define BH_OFF 16384
#define STAGE  32768
#define NSTG   3
#define SMEM_DYN (NSTG * STAGE)   // 96KB -> 2 CTAs/SM (all 256 CTAs co-resident)

// ---------------- static device scratch ----------------
__device__ __half g_x[(PH + 1) * (size_t)SLAB];   // x_t (fp16), t=0..PH
__device__ __half g_w [FOURH * HID];   // fp16(W_ih + W_hh), permuted
__device__ __half g_w0[FOURH * HID];   // fp16(W_ih), permuted (step 0)
__device__ float g_bp[FOURH];
__device__ float g_c[(size_t)BSZ * HID];
__device__ unsigned g_bar;             // grid-barrier counter (zeroed each launch)

// ---------------- helpers ----------------
__device__ __forceinline__ uint32_t smem_u32(const void* p) {
    uint32_t a;
    asm("{ .reg .u64 t; cvta.to.shared.u64 t, %1; cvt.u32.u64 %0, t; }" : "=r"(a) : "l"(p));
    return a;
}
// 128B rows, 8 x 16B quads, XOR-swizzled: conflict-free for cp.async stores and ldmatrix
__device__ __forceinline__ uint32_t smoff64(int row, int q) {
    return (uint32_t)((row << 7) + (((q) ^ (row & 7)) << 4));
}
__device__ __forceinline__ void cp16(uint32_t dst, const void* src) {
    asm volatile("cp.async.cg.shared.global [%0], [%1], 16;" :: "r"(dst), "l"(src));
}
__device__ __forceinline__ void cp_commit() { asm volatile("cp.async.commit_group;"); }
template <int N>
__device__ __forceinline__ void cp_wait() {
    asm volatile("cp.async.wait_group %0;" :: "n"(N) : "memory");
}
__device__ __forceinline__ void ldsm4(uint32_t* r, uint32_t addr) {
    asm volatile("ldmatrix.sync.aligned.m8n8.x4.shared.b16 {%0,%1,%2,%3}, [%4];"
        : "=r"(r[0]), "=r"(r[1]), "=r"(r[2]), "=r"(r[3]) : "r"(addr));
}
__device__ __forceinline__ void mma16816(float* c, const uint32_t* a,
                                         uint32_t b0, uint32_t b1) {
    asm volatile(
        "mma.sync.aligned.m16n8k16.row.col.f32.f16.f16.f32 "
        "{%0,%1,%2,%3}, {%4,%5,%6,%7}, {%8,%9}, {%0,%1,%2,%3};"
        : "+f"(c[0]), "+f"(c[1]), "+f"(c[2]), "+f"(c[3])
        : "r"(a[0]), "r"(a[1]), "r"(a[2]), "r"(a[3]), "r"(b0), "r"(b1));
}

// ---------------- prep ----------------
// W row r=q*512+hu -> rp = (hu/32)*128 + q*32 + (hu%32): N-tile nb holds 32 units x 4 gates
__global__ void prep_w(const float* __restrict__ Wih, const float* __restrict__ Whh,
                       const float* __restrict__ bih, const float* __restrict__ bhh) {
    int idx = blockIdx.x * blockDim.x + threadIdx.x;
    if (idx >= FOURH * HID) return;
    int r = idx / HID, k = idx - r * HID;
    int q = r >> 9, hu = r & 511;
    int rp = ((hu >> 5) << 7) + (q << 5) + (hu & 31);
    size_t o = (size_t)rp * HID + k;
    g_w0[o] = __float2half_rn(Wih[idx]);
    g_w [o] = __float2half_rn(Wih[idx] + Whh[idx]);
    if (k == 0) g_bp[rp] = bih[r] + bhh[r];
}
__global__ void prep_z(const float* __restrict__ z) {
    int i = blockIdx.x * blockDim.x + threadIdx.x;
    if (i == 0) g_bar = 0u;                 // reset grid barrier every launch
    if (i >= BSZ * HID) return;
    g_x[i] = __float2half_rn(z[i]);
}

// ---------------- persistent kernel: all PH steps, grid barrier between steps ----------
// 8 warps: wm = warp>>2 (M 2x64), wn = warp&3. Warp wn owns n8-blocks {wn, wn+4, wn+8,
// wn+12} = gates i,f,g,o of hidden units [8wn, 8wn+8): epilogue fully register-local.
__global__ __launch_bounds__(NTHR, 2)
void lstm_persist() {
    extern __shared__ char dyn[];
    __shared__ float bias_sm[TN];
    const int tid = threadIdx.x;
    const int lane = tid & 31, warp = tid >> 5;
    const int wm = warp >> 2, wn = warp & 3;
    const int mb = blockIdx.x, nb = blockIdx.y;

    if (tid < TN) bias_sm[tid] = g_bp[nb * TN + tid];

    // ---- cp.async plan: rows 0..31 (+32*i), quads 0..7 ----
    const int lrow = tid >> 3, lq = tid & 7;
    const size_t a_goff = (size_t)(mb * TM + lrow) * HID + lq * 8;
    const size_t b_goff = (size_t)(nb * TN + lrow) * HID + lq * 8;
    const uint32_t a_dst0 = AH_OFF + smoff64(lrow, lq);  // +4096 per 32 rows
    const uint32_t b_dst0 = BH_OFF + smoff64(lrow, lq);

    // precomputed swizzled ldsm base offsets (stage-relative)
    const int a_row = wm * 64 + (lane & 7) + ((lane >> 3) & 1) * 8;
    const int b_row = 8 * (4 * (lane >> 3) + wn) + (lane & 7);   // n8 block = g*4 + wn
    uint32_t a_base[4], b_base[4][2];
#pragma unroll
    for (int s = 0; s < 4; ++s) {
        a_base[s] = AH_OFF + smoff64(a_row, 2 * s + (lane >> 4));
        b_base[s][0] = BH_OFF + smoff64(b_row, 2 * s);
        b_base[s][1] = BH_OFF + smoff64(b_row, 2 * s + 1);
    }

    // epilogue lane constants
    const int gq = lane >> 2, sq = lane & 3;
    const int hu = nb * 32 + 8 * wn + 2 * sq;

    // ---- prologue: A+B for chunks 0,1 of step 0 (B from g_w0) ----
#pragma unroll
    for (int p = 0; p < 2; ++p) {
        uint32_t sb = smem_u32(dyn + p * STAGE);
        int k0 = p * KC;
#pragma unroll
        for (int i = 0; i < 4; ++i) {
            cp16(sb + a_dst0 + 4096 * i, g_x  + a_goff + (size_t)(32 * i) * HID + k0);
            cp16(sb + b_dst0 + 4096 * i, g_w0 + b_goff + (size_t)(32 * i) * HID + k0);
        }
        cp_commit();
    }

    int sg = 0;   // stage of next chunk to consume ( = (8t+c) % 3, rotates continuously )
#pragma unroll 1
    for (int t = 0; t < PH; ++t) {
        const __half* Ab = g_x + (size_t)t * SLAB + a_goff;
        const __half* Bb = (t == 0 ? g_w0 : g_w) + b_goff;
        const __half* Bn = g_w + b_goff;              // next step's B (always merged W)

        float acc[4][4][4];
#pragma unroll
        for (int mi = 0; mi < 4; ++mi)
#pragma unroll
            for (int g = 0; g < 4; ++g)
#pragma unroll
                for (int r = 0; r < 4; ++r) acc[mi][g][r] = 0.f;

#pragma unroll 1
        for (int c = 0; c < NCH; ++c) {
            cp_wait<1>();
            __syncthreads();             // chunk c resident; overwritten stage drained
            int st2 = sg + 2; if (st2 >= NSTG) st2 -= NSTG;
            uint32_t sb = smem_u32(dyn + st2 * STAGE);
            if (c < NCH - 2) {           // A+B of chunk c+2, this step
                int k0 = (c + 2) * KC;
#pragma unroll
                for (int i = 0; i < 4; ++i) {
                    cp16(sb + a_dst0 + 4096 * i, Ab + (size_t)(32 * i) * HID + k0);
                    cp16(sb + b_dst0 + 4096 * i, Bb + (size_t)(32 * i) * HID + k0);
                }
            } else if (t + 1 < PH) {     // B-only of chunk c-6 of NEXT step
                int k0 = (c - (NCH - 2)) * KC;
#pragma unroll
                for (int i = 0; i < 4; ++i)
                    cp16(sb + b_dst0 + 4096 * i, Bn + (size_t)(32 * i) * HID + k0);
            }
            cp_commit();                 // exactly one group per slot (possibly empty)

            uint32_t st = smem_u32(dyn + sg * STAGE);
#pragma unroll
            for (int s = 0; s < 4; ++s) {
                uint32_t r0[4], r1[4];
                ldsm4(r0, st + b_base[s][0]);
                ldsm4(r1, st + b_base[s][1]);
#pragma unroll
                for (int mi = 0; mi < 4; ++mi) {
                    uint32_t ah[4];
                    ldsm4(ah, st + a_base[s] + 2048 * mi);
#pragma unroll
                    for (int g = 0; g < 4; ++g)
                        mma16816(acc[mi][g], ah, r0[g], r1[g]);
                }
            }
            ++sg; if (sg >= NSTG) sg = 0;
        }

        // ---- fused LSTM epilogue ----
        __half* x_o = g_x + (size_t)(t + 1) * SLAB;
#pragma unroll
        for (int mi = 0; mi < 4; ++mi) {
#pragma unroll
            for (int rw = 0; rw < 2; ++rw) {
                int row = mb * TM + wm * 64 + mi * 16 + gq + rw * 8;
                size_t off = (size_t)row * HID + hu;
                float2 cold = (t == 0) ? make_float2(0.f, 0.f) : *(const float2*)(g_c + off);
                float hn[2], cn[2];
#pragma unroll
                for (int e = 0; e < 2; ++e) {
                    int r = 2 * rw + e, u = 8 * wn + 2 * sq + e;
                    float gi = acc[mi][0][r] + bias_sm[u];
                    float gf = acc[mi][1][r] + bias_sm[32 + u];
                    float gg = acc[mi][2][r] + bias_sm[64 + u];
                    float go = acc[mi][3][r] + bias_sm[96 + u];
                    float co = e ? cold.y : cold.x;
                    float si = 1.f / (1.f + __expf(-gi));
                    float sf = 1.f / (1.f + __expf(-gf));
                    float so = 1.f / (1.f + __expf(-go));
                    float tg = 2.f / (1.f + __expf(-2.f * gg)) - 1.f;
                    cn[e] = fmaf(sf, co, si * tg);
                    float tc = 2.f / (1.f + __expf(-2.f * cn[e])) - 1.f;
                    hn[e] = so * tc;
                }
                *(float2*)(g_c + off) = make_float2(cn[0], cn[1]);
                __half2 h2;
                h2.x = __float2half_rn(hn[0]); h2.y = __float2half_rn(hn[1]);
                *(__half2*)(x_o + off) = h2;
            }
        }

        // ---- grid barrier + post-barrier A-only refill ----
        if (t + 1 < PH) {
            __threadfence();             // release: h stores -> L2 (GPU scope)
            __syncthreads();
            if (tid == 0) {
                atomicAdd(&g_bar, 1u);
                unsigned target = (unsigned)NCTA * (unsigned)(t + 1);
                while (*(volatile unsigned*)&g_bar < target) __nanosleep(64);
            }
            __syncthreads();
            // A of chunks 0,1 of step t+1 (B already staged by the c>=6 slots above).
            // cp.async.cg bypasses L1, reads coherent L2 data.
            const __half* An = g_x + (size_t)(t + 1) * SLAB + a_goff;
#pragma unroll
            for (int p = 0; p < 2; ++p) {
                int stp = sg + p; if (stp >= NSTG) stp -= NSTG;
                uint32_t sb2 = smem_u32(dyn + stp * STAGE);
                int k0 = p * KC;
#pragma unroll
                for (int i = 0; i < 4; ++i)
                    cp16(sb2 + a_dst0 + 4096 * i, An + (size_t)(32 * i) * HID + k0);
                cp_commit();
            }
        }
    }
}

// ---------------- final projection: all 32 steps in one kernel ----------------
__global__ void out_all(const float* __restrict__ Wd, const float* __restrict__ bd,
                        float* __restrict__ Y) {
    int wg = blockIdx.x * 8 + (threadIdx.x >> 5);
    int lane = threadIdx.x & 31;
    int t = wg & (PH - 1), row = wg >> 5;
    const __half* xp = g_x + (size_t)(t + 1) * SLAB + (size_t)row * HID;
    float s0 = 0.f, s1 = 0.f;
    for (int k = lane; k < HID; k += 32) {
        float hv = __half2float(xp[k]);
        s0 = fmaf(hv, Wd[k], s0);
        s1 = fmaf(hv, Wd[HID + k], s1);
    }
#pragma unroll
    for (int o = 16; o > 0; o >>= 1) {
        s0 += __shfl_xor_sync(0xffffffffu, s0, o);
        s1 += __shfl_xor_sync(0xffffffffu, s1, o);
    }
    if (lane == 0) {
        Y[(size_t)row * (PH * 2) + t * 2 + 0] = s0 + bd[0];
        Y[(size_t)row * (PH * 2) + t * 2 + 1] = s1 + bd[1];
    }
}

extern "C" void kernel_launch(void* const* d_in, const int* in_sizes, int n_in,
                              void* d_out, int out_size) {
    // metadata order: hist, z, W_ih, W_hh, b_ih, b_hh, W_d, b_d
    const float* z   = (const float*)d_in[1];
    const float* Wih = (const float*)d_in[2];
    const float* Whh = (const float*)d_in[3];
    const float* bih = (const float*)d_in[4];
    const float* bhh = (const float*)d_in[5];
    const float* Wd  = (const float*)d_in[6];
    const float* bd  = (const float*)d_in[7];
    float* Y = (float*)d_out;

    cudaFuncSetAttribute(lstm_persist, cudaFuncAttributeMaxDynamicSharedMemorySize, SMEM_DYN);

    prep_w<<<(FOURH * HID + 255) / 256, 256>>>(Wih, Whh, bih, bhh);
    prep_z<<<(BSZ * HID + 255) / 256, 256>>>(z);

    dim3 grid(BSZ / TM, FOURH / TN);   // 16 x 16 = 256 CTAs, all co-resident (2/SM)
    lstm_persist<<<grid, NTHR, SMEM_DYN>>>();
    out_all<<<BSZ * PH / 8, 256>>>(Wd, bd, Y);
}

// round 12
// speedup vs baseline: 1.0874x; 1.0874x over previous
#include <cuda_runtime.h>
#include <cuda_fp16.h>
#include <math.h>
#include <stdint.h>

#define HID   512
#define PH    32
#define BSZ   2048
#define FOURH 2048
#define SLAB  (BSZ * HID)

#define TM 128
#define TN 128
#define KC 64
#define NCH (HID / KC)   // 8 k-chunks
#define NTHR 256
#define NNB  (FOURH / TN)   // 16 nb tiles

// stage layout (bytes): A 128x64 fp16 = 16KB, B 128x64 fp16 = 16KB
#define AH_OFF 0
#define BH_OFF 16384
#define STAGE  32768
#define NSTG   3
#define SMEM_DYN (NSTG * STAGE)   // 96KB -> 2 CTAs/SM

// ---------------- static device scratch ----------------
__device__ __half g_x[(PH + 1) * (size_t)SLAB];   // x_t (fp16), t=0..PH
__device__ __half g_w [FOURH * HID];   // fp16(W_ih + W_hh), permuted
__device__ __half g_w0[FOURH * HID];   // fp16(W_ih), permuted (step 0)
__device__ float g_bp[FOURH];
__device__ float g_c[(size_t)BSZ * HID];
__device__ float g_part[(size_t)PH * NNB * BSZ * 2];   // projection partials

// ---------------- helpers ----------------
__device__ __forceinline__ uint32_t smem_u32(const void* p) {
    uint32_t a;
    asm("{ .reg .u64 t; cvta.to.shared.u64 t, %1; cvt.u32.u64 %0, t; }" : "=r"(a) : "l"(p));
    return a;
}
// 128B rows, 8 x 16B quads, XOR-swizzled: conflict-free for cp.async stores and ldmatrix
__device__ __forceinline__ uint32_t smoff64(int row, int q) {
    return (uint32_t)((row << 7) + (((q) ^ (row & 7)) << 4));
}
__device__ __forceinline__ void cp16(uint32_t dst, const void* src) {
    asm volatile("cp.async.cg.shared.global [%0], [%1], 16;" :: "r"(dst), "l"(src));
}
__device__ __forceinline__ void cp_commit() { asm volatile("cp.async.commit_group;"); }
template <int N>
__device__ __forceinline__ void cp_wait() {
    asm volatile("cp.async.wait_group %0;" :: "n"(N) : "memory");
}
__device__ __forceinline__ void ldsm4(uint32_t* r, uint32_t addr) {
    asm volatile("ldmatrix.sync.aligned.m8n8.x4.shared.b16 {%0,%1,%2,%3}, [%4];"
        : "=r"(r[0]), "=r"(r[1]), "=r"(r[2]), "=r"(r[3]) : "r"(addr));
}
__device__ __forceinline__ void mma16816(float* c, const uint32_t* a,
                                         uint32_t b0, uint32_t b1) {
    asm volatile(
        "mma.sync.aligned.m16n8k16.row.col.f32.f16.f16.f32 "
        "{%0,%1,%2,%3}, {%4,%5,%6,%7}, {%8,%9}, {%0,%1,%2,%3};"
        : "+f"(c[0]), "+f"(c[1]), "+f"(c[2]), "+f"(c[3])
        : "r"(a[0]), "r"(a[1]), "r"(a[2]), "r"(a[3]), "r"(b0), "r"(b1));
}

// ---------------- prep ----------------
// W row r=q*512+hu -> rp = (hu/32)*128 + q*32 + (hu%32): N-tile nb holds 32 units x 4 gates
__global__ void prep_w(const float* __restrict__ Wih, const float* __restrict__ Whh,
                       const float* __restrict__ bih, const float* __restrict__ bhh) {
    int idx = blockIdx.x * blockDim.x + threadIdx.x;
    if (idx >= FOURH * HID) return;
    int r = idx / HID, k = idx - r * HID;
    int q = r >> 9, hu = r & 511;
    int rp = ((hu >> 5) << 7) + (q << 5) + (hu & 31);
    size_t o = (size_t)rp * HID + k;
    g_w0[o] = __float2half_rn(Wih[idx]);
    g_w [o] = __float2half_rn(Wih[idx] + Whh[idx]);
    if (k == 0) g_bp[rp] = bih[r] + bhh[r];
}
__global__ void prep_z(const float* __restrict__ z) {
    int i = blockIdx.x * blockDim.x + threadIdx.x;
    if (i >= BSZ * HID) return;
    g_x[i] = __float2half_rn(z[i]);
}

// ---------------- per-step: gates = X @ W^T (fp16 mma.sync) + LSTM + projection partials --
// 8 warps: wm = warp>>2 (M 2x64), wn = warp&3. Warp wn owns n8-blocks {wn, wn+4, wn+8,
// wn+12} = gates i,f,g,o of hidden units [8wn, 8wn+8): epilogue fully register-local.
__global__ __launch_bounds__(NTHR, 2)
void step_kernel(const __half* __restrict__ x, const __half* __restrict__ w,
                 __half* __restrict__ x_o, const float* __restrict__ Wd, int t) {
    extern __shared__ char dyn[];
    __shared__ float bias_sm[TN];
    __shared__ float wd_sm[2][32];
    __shared__ float part_sm[2][4][8][4][2][2];   // [wm][wn][gq][mi][rw][o]
    const int tid = threadIdx.x;
    const int lane = tid & 31, warp = tid >> 5;
    const int wm = warp >> 2, wn = warp & 3;
    const int mb = blockIdx.x, nb = blockIdx.y;

    if (tid < TN) bias_sm[tid] = g_bp[nb * TN + tid];
    if (tid < 64) wd_sm[tid >> 5][tid & 31] = Wd[(tid >> 5) * HID + nb * 32 + (tid & 31)];

    // ---- cp.async plan: rows 0..31 (+32*i), quads 0..7; 4 A + 4 B 16B-copies/thread ----
    const int lrow = tid >> 3, lq = tid & 7;
    const __half* a_src = x + (size_t)(mb * TM + lrow) * HID + lq * 8;
    const __half* b_src = w + (size_t)(nb * TN + lrow) * HID + lq * 8;
    const uint32_t a_dst0 = AH_OFF + smoff64(lrow, lq);  // +4096 per 32 rows
    const uint32_t b_dst0 = BH_OFF + smoff64(lrow, lq);

    float acc[4][4][4];   // [mi][gate][frag]
#pragma unroll
    for (int mi = 0; mi < 4; ++mi)
#pragma unroll
        for (int g = 0; g < 4; ++g)
#pragma unroll
            for (int r = 0; r < 4; ++r) acc[mi][g][r] = 0.f;

    // precomputed swizzled ldsm base offsets (stage-relative)
    const int a_row = wm * 64 + (lane & 7) + ((lane >> 3) & 1) * 8;
    const int b_row = 8 * (4 * (lane >> 3) + wn) + (lane & 7);   // n8 block = g*4 + wn
    uint32_t a_base[4], b_base[4][2];
#pragma unroll
    for (int s = 0; s < 4; ++s) {
        a_base[s] = AH_OFF + smoff64(a_row, 2 * s + (lane >> 4));
        b_base[s][0] = BH_OFF + smoff64(b_row, 2 * s);
        b_base[s][1] = BH_OFF + smoff64(b_row, 2 * s + 1);
    }

#pragma unroll
    for (int p = 0; p < 2; ++p) {
        uint32_t sb = smem_u32(dyn + p * STAGE);
        int k0 = p * KC;
#pragma unroll
        for (int i = 0; i < 4; ++i) {
            cp16(sb + a_dst0 + 4096 * i, a_src + (size_t)(32 * i) * HID + k0);
            cp16(sb + b_dst0 + 4096 * i, b_src + (size_t)(32 * i) * HID + k0);
        }
        cp_commit();
    }

#pragma unroll
    for (int c = 0; c < NCH; ++c) {
        if (c + 2 < NCH) cp_wait<1>(); else cp_wait<0>();
        __syncthreads();                 // chunk c resident; stage (c-1)%3 drained
        if (c + 2 < NCH) {
            uint32_t sb = smem_u32(dyn + ((c + 2) % 3) * STAGE);
            int k0 = (c + 2) * KC;
#pragma unroll
            for (int i = 0; i < 4; ++i) {
                cp16(sb + a_dst0 + 4096 * i, a_src + (size_t)(32 * i) * HID + k0);
                cp16(sb + b_dst0 + 4096 * i, b_src + (size_t)(32 * i) * HID + k0);
            }
            cp_commit();
        }
        uint32_t st = smem_u32(dyn + (c % 3) * STAGE);
#pragma unroll
        for (int s = 0; s < 4; ++s) {
            uint32_t r0[4], r1[4];           // B frags: r0 = k0-7, r1 = k8-15, per gate
            ldsm4(r0, st + b_base[s][0]);
            ldsm4(r1, st + b_base[s][1]);
#pragma unroll
            for (int mi = 0; mi < 4; ++mi) {
                uint32_t ah[4];
                ldsm4(ah, st + a_base[s] + 2048 * mi);
#pragma unroll
                for (int g = 0; g < 4; ++g)
                    mma16816(acc[mi][g], ah, r0[g], r1[g]);
            }
        }
    }

    // ---- fused LSTM epilogue + projection partials ----
    const int gq = lane >> 2, sq = lane & 3;
    const int uu = 8 * wn + 2 * sq;          // local hidden index (0..31)
    const int hu = nb * 32 + uu;
#pragma unroll
    for (int mi = 0; mi < 4; ++mi) {
#pragma unroll
        for (int rw = 0; rw < 2; ++rw) {
            int row = mb * TM + wm * 64 + mi * 16 + gq + rw * 8;
            size_t off = (size_t)row * HID + hu;
            float2 cold = (t == 0) ? make_float2(0.f, 0.f) : *(const float2*)(g_c + off);
            float hn[2], cn[2];
#pragma unroll
            for (int e = 0; e < 2; ++e) {
                int r = 2 * rw + e, u = uu + e;
                float gi = acc[mi][0][r] + bias_sm[u];
                float gf = acc[mi][1][r] + bias_sm[32 + u];
                float gg = acc[mi][2][r] + bias_sm[64 + u];
                float go = acc[mi][3][r] + bias_sm[96 + u];
                float co = e ? cold.y : cold.x;
                float si = 1.f / (1.f + __expf(-gi));
                float sf = 1.f / (1.f + __expf(-gf));
                float so = 1.f / (1.f + __expf(-go));
                float tg = 2.f / (1.f + __expf(-2.f * gg)) - 1.f;
                cn[e] = fmaf(sf, co, si * tg);
                float tc = 2.f / (1.f + __expf(-2.f * cn[e])) - 1.f;
                hn[e] = so * tc;
            }
            *(float2*)(g_c + off) = make_float2(cn[0], cn[1]);
            __half2 h2;
            h2.x = __float2half_rn(hn[0]); h2.y = __float2half_rn(hn[1]);
            *(__half2*)(x_o + off) = h2;
            // projection partials: reduce over the 4 sq-lanes (same row, different hu)
            float p0 = hn[0] * wd_sm[0][uu] + hn[1] * wd_sm[0][uu + 1];
            float p1 = hn[0] * wd_sm[1][uu] + hn[1] * wd_sm[1][uu + 1];
            p0 += __shfl_xor_sync(0xffffffffu, p0, 1);
            p0 += __shfl_xor_sync(0xffffffffu, p0, 2);
            p1 += __shfl_xor_sync(0xffffffffu, p1, 1);
            p1 += __shfl_xor_sync(0xffffffffu, p1, 2);
            if (sq == 0) {
                part_sm[wm][wn][gq][mi][rw][0] = p0;
                part_sm[wm][wn][gq][mi][rw][1] = p1;
            }
        }
    }
    __syncthreads();
    // 256 threads: one (wm,gq,mi,rw,o) entry each, fixed-order sum over wn
    {
        int o  = tid & 1;
        int rw = (tid >> 1) & 1;
        int mi = (tid >> 2) & 3;
        int gq2 = (tid >> 4) & 7;
        int wm2 = tid >> 7;
        float s = part_sm[wm2][0][gq2][mi][rw][o] + part_sm[wm2][1][gq2][mi][rw][o]
                + part_sm[wm2][2][gq2][mi][rw][o] + part_sm[wm2][3][gq2][mi][rw][o];
        int row = mb * TM + wm2 * 64 + mi * 16 + gq2 + rw * 8;
        g_part[(((size_t)t * NNB + nb) * BSZ + row) * 2 + o] = s;
    }
}

// ---------------- final: reduce projection partials over nb ----------------
__global__ void out_reduce(const float* __restrict__ bd, float* __restrict__ Y) {
    int i = blockIdx.x * 256 + threadIdx.x;    // i = (t*2+o)*BSZ + row
    if (i >= PH * 2 * BSZ) return;
    int row = i & (BSZ - 1);
    int to = i >> 11;                           // t*2+o
    int o = to & 1, t = to >> 1;
    float s = bd[o];
#pragma unroll
    for (int nb = 0; nb < NNB; ++nb)
        s += g_part[(((size_t)t * NNB + nb) * BSZ + row) * 2 + o];
    Y[(size_t)row * (PH * 2) + t * 2 + o] = s;
}

extern "C" void kernel_launch(void* const* d_in, const int* in_sizes, int n_in,
                              void* d_out, int out_size) {
    // metadata order: hist, z, W_ih, W_hh, b_ih, b_hh, W_d, b_d
    const float* z   = (const float*)d_in[1];
    const float* Wih = (const float*)d_in[2];
    const float* Whh = (const float*)d_in[3];
    const float* bih = (const float*)d_in[4];
    const float* bhh = (const float*)d_in[5];
    const float* Wd  = (const float*)d_in[6];
    const float* bd  = (const float*)d_in[7];
    float* Y = (float*)d_out;

    __half *xp, *wp, *wp0;
    cudaGetSymbolAddress((void**)&xp,  g_x);
    cudaGetSymbolAddress((void**)&wp,  g_w);
    cudaGetSymbolAddress((void**)&wp0, g_w0);

    cudaFuncSetAttribute(step_kernel, cudaFuncAttributeMaxDynamicSharedMemorySize, SMEM_DYN);

    prep_w<<<(FOURH * HID + 255) / 256, 256>>>(Wih, Whh, bih, bhh);
    prep_z<<<(BSZ * HID + 255) / 256, 256>>>(z);

    dim3 grid(BSZ / TM, FOURH / TN);   // 16 x 16 = 256 CTAs, 2 per SM
    for (int t = 0; t < PH; ++t) {
        step_kernel<<<grid, NTHR, SMEM_DYN>>>(xp + (size_t)t * SLAB,
                                              t == 0 ? wp0 : wp,
                                              xp + (size_t)(t + 1) * SLAB, Wd, t);
    }
    out_reduce<<<(PH * 2 * BSZ + 255) / 256, 256>>>(bd, Y);
}